// round 14
// baseline (speedup 1.0000x reference)
#include <cuda_runtime.h>
#include <cuda_bf16.h>
#include <cuda_fp16.h>
#include <cstdint>

// ---------------- scratch (device globals; no runtime allocation) ----------------
__device__ float g_x1[(size_t)8 * 1024 * 40 * 64];   // conv0 out [B,1024,40,64]
__device__ float g_x2[(size_t)8 * 512 * 20 * 64];    // conv1 out [B,512,20,64]
__device__ float g_p [(size_t)4096 * 32];            // proj out  [B*S,32]
__device__ float g_emb [(size_t)4096 * 256];         // primary caps [B*S,32,8]
__device__ float g_emb2[(size_t)4096 * 256];         // conv caps    [B*S,32,8]
__device__ uint4 g_ubuf[2][(size_t)2048 * 96 * 32];  // u_hat fp16 double buffer (2x100MB)
__device__ ulonglong2 g_wq1[9 * 16 * 64];            // conv1 w1 packed (ic quads, 2x f32x2)
__device__ ulonglong2 g_wq2[9 * 16 * 64];            // conv1 w2 packed
__device__ unsigned long long g_pwp[640 * 32];       // proj w packed (k pairs)
__device__ float g_ec[256];                          // layer-0 bias-routing constant (post-LN)
__device__ float g_outc[31];                         // layer-1 bias-routing constant (final)

#define CHUNK 2048
#define NCHUNK 2

// ---------------- helpers ----------------
__device__ __forceinline__ unsigned long long pack2(float x, float y) {
    unsigned long long r;
    asm("mov.b64 %0, {%1, %2};" : "=l"(r) : "f"(x), "f"(y));
    return r;
}
__device__ __forceinline__ void fma2(unsigned long long& c, unsigned long long a, unsigned long long b) {
    asm("fma.rn.f32x2 %0, %1, %2, %0;" : "+l"(c) : "l"(a), "l"(b));
}
__device__ __forceinline__ float2 unpack2(unsigned long long v) {
    float lo, hi;
    asm("mov.b64 {%0, %1}, %2;" : "=f"(lo), "=f"(hi) : "l"(v));
    return make_float2(lo, hi);
}
__device__ __forceinline__ float2 h2f(unsigned u) {
    __half2 h = *reinterpret_cast<__half2*>(&u);
    return __half22float2(h);
}
__device__ __forceinline__ unsigned f2h(float a, float b) {
    __half2 h = __floats2half2_rn(a, b);
    return *reinterpret_cast<unsigned*>(&h);
}

__device__ __forceinline__ void blockReduceSum2(float& a, float& b) {
    __shared__ float red[16];
    int lane = threadIdx.x & 31, w = threadIdx.x >> 5;
#pragma unroll
    for (int o = 16; o; o >>= 1) {
        a += __shfl_xor_sync(0xffffffffu, a, o);
        b += __shfl_xor_sync(0xffffffffu, b, o);
    }
    if (lane == 0) { red[w] = a; red[8 + w] = b; }
    __syncthreads();
    a = red[0] + red[1] + red[2] + red[3] + red[4] + red[5] + red[6] + red[7];
    b = red[8] + red[9] + red[10] + red[11] + red[12] + red[13] + red[14] + red[15];
    __syncthreads();
}

// shared routing core: u in fp32 registers, softmax over o = lanes
__device__ __forceinline__ float route_core(float (&uj)[12][8], float mask,
                                            float* sred, float* sv, int tid)
{
    int w = tid >> 5, o = tid & 31;
    float bij[12];
#pragma unroll
    for (int jj = 0; jj < 12; jj++) bij[jj] = 0.f;
    float v_od = 0.f;
    for (int it = 0; it < 3; it++) {
        float sp8[8] = {0, 0, 0, 0, 0, 0, 0, 0};
#pragma unroll
        for (int jj = 0; jj < 12; jj++) {
            float e = __expf(bij[jj] + mask);
            float ssum = e;
#pragma unroll
            for (int off = 16; off; off >>= 1)
                ssum += __shfl_xor_sync(0xffffffffu, ssum, off);
            float c = __fdividef(e, ssum);
#pragma unroll
            for (int d = 0; d < 8; d++) sp8[d] = fmaf(c, uj[jj][d], sp8[d]);
        }
        *reinterpret_cast<float4*>(&sred[w * 256 + o * 8]) =
            make_float4(sp8[0], sp8[1], sp8[2], sp8[3]);
        *reinterpret_cast<float4*>(&sred[w * 256 + o * 8 + 4]) =
            make_float4(sp8[4], sp8[5], sp8[6], sp8[7]);
        __syncthreads();
        float s_od = 0.f;
#pragma unroll
        for (int w2 = 0; w2 < 8; w2++) s_od += sred[w2 * 256 + tid];
        float sq = s_od * s_od;
        sq += __shfl_xor_sync(0xffffffffu, sq, 1);
        sq += __shfl_xor_sync(0xffffffffu, sq, 2);
        sq += __shfl_xor_sync(0xffffffffu, sq, 4);
        v_od = s_od * (sq / (1.f + sq) * rsqrtf(sq + 1e-6f));
        sv[tid] = v_od;
        __syncthreads();
        if (it < 2) {
            float vv[8];
            *reinterpret_cast<float4*>(&vv[0]) = *reinterpret_cast<const float4*>(&sv[o * 8]);
            *reinterpret_cast<float4*>(&vv[4]) = *reinterpret_cast<const float4*>(&sv[o * 8 + 4]);
#pragma unroll
            for (int jj = 0; jj < 12; jj++) {
                float acc = 0.f;
#pragma unroll
                for (int d = 0; d < 8; d++) acc = fmaf(uj[jj][d], vv[d], acc);
                bij[jj] += acc;
            }
        }
    }
    return v_od;
}

// ---------------- K0: weight pre-packing ----------------
__global__ void __launch_bounds__(256) k_prep(const float* __restrict__ w1,
                                              const float* __restrict__ w2,
                                              const float* __restrict__ pw)
{
    int idx = blockIdx.x * 256 + threadIdx.x;
    if (idx < 9 * 16 * 64) {
        int oc = idx & 63, r = idx >> 6;
        int khkw = r >> 4, ic4 = r & 15;
        int base = (khkw * 64 + ic4 * 4) * 64 + oc;
        ulonglong2 v1, v2;
        v1.x = pack2(w1[base], w1[base + 64]);
        v1.y = pack2(w1[base + 128], w1[base + 192]);
        v2.x = pack2(w2[base], w2[base + 64]);
        v2.y = pack2(w2[base + 128], w2[base + 192]);
        g_wq1[idx] = v1;
        g_wq2[idx] = v2;
    }
    int pidx = idx - 9 * 16 * 64;
    if (pidx >= 0 && pidx < 640 * 32) {
        int col = pidx & 31, q = pidx >> 5;
        g_pwp[pidx] = pack2(pw[(2 * q) * 32 + col], pw[(2 * q + 1) * 32 + col]);
    }
}

// ---------------- K0b: bias-only routing constants (1 block) ----------------
__global__ void __launch_bounds__(256) k_const(const float* __restrict__ B0,
                                               const float* __restrict__ W1,
                                               const float* __restrict__ B1)
{
    __shared__ float sred[8 * 256];
    __shared__ float sv[256];
    __shared__ float sec[256];
    __shared__ float slen[32];
    int tid = threadIdx.x;
    int w = tid >> 5, o = tid & 31;

    float uj[12][8];
#pragma unroll
    for (int jj = 0; jj < 12; jj++)
#pragma unroll
        for (int d = 0; d < 8; d++)
            uj[jj][d] = B0[(((size_t)(w * 12 + jj) * 32) + o) * 8 + d];

    float v_od = route_core(uj, 0.f, sred, sv, tid);

    float a = v_od, b2 = v_od * v_od;
    blockReduceSum2(a, b2);
    float mu = a * (1.f / 256.f);
    float var = b2 * (1.f / 256.f) - mu * mu;
    float ec = (v_od - mu) * rsqrtf(var + 1e-3f);
    sec[tid] = ec;
    g_ec[tid] = ec;
    __syncthreads();

    float uj2[12][8];
#pragma unroll
    for (int jj = 0; jj < 12; jj++) {
        int i = w * 12 + jj, ii = i & 31;
#pragma unroll
        for (int d = 0; d < 8; d++) {
            float acc = 0.f;
            if (o < 31) {
                acc = B1[((size_t)i * 31 + o) * 8 + d];
                const float* Wr = &W1[(((size_t)i * 31 + o) * 8 + d) * 8];
#pragma unroll
                for (int k = 0; k < 8; k++) acc = fmaf(Wr[k], sec[ii * 8 + k], acc);
            }
            uj2[jj][d] = acc;
        }
    }
    __syncthreads();
    float mask = (o == 0 || o >= 31) ? -1e9f : 0.f;
    v_od = route_core(uj2, mask, sred, sv, tid);

    int oo = tid >> 3, dd = tid & 7;
    bool valid = (oo < 31);
    float x = valid ? v_od : 0.f;
    a = x; b2 = x * x;
    blockReduceSum2(a, b2);
    mu = a * (1.f / 248.f);
    var = b2 * (1.f / 248.f) - mu * mu;
    float vn = valid ? (x - mu) * rsqrtf(var + 1e-3f) : 0.f;
    float sq = vn * vn;
    sq += __shfl_xor_sync(0xffffffffu, sq, 1);
    sq += __shfl_xor_sync(0xffffffffu, sq, 2);
    sq += __shfl_xor_sync(0xffffffffu, sq, 4);
    if (dd == 0) slen[oo] = sqrtf(sq + 1e-6f);
    __syncthreads();
    if (tid < 32) {
        float l = (tid < 31) ? slen[tid] : 0.f;
        float sa = l, sb = l * l;
#pragma unroll
        for (int off = 16; off; off >>= 1) {
            sa += __shfl_xor_sync(0xffffffffu, sa, off);
            sb += __shfl_xor_sync(0xffffffffu, sb, off);
        }
        float mu2 = sa / 31.f;
        float var2 = sb / 31.f - mu2 * mu2;
        if (tid < 31) g_outc[tid] = (l - mu2) * rsqrtf(var2 + 1e-3f);
    }
}

// ---------------- K1: conv0 maxout + time mask (4 output rows per block) ----------------
__global__ void __launch_bounds__(256) k_conv0(
    const float* __restrict__ in,
    const float* __restrict__ w1, const float* __restrict__ b1,
    const float* __restrict__ w2, const float* __restrict__ b2,
    const int* __restrict__ lens)
{
    __shared__ float sw1[576], sw2[576], sb[128];
    __shared__ float sin_[9][80];
    int tid = threadIdx.x;
    int b   = blockIdx.x >> 8;
    int oh0 = (blockIdx.x & 255) << 2;
    int vl = (lens[b] + 1) >> 1;
    int c = tid & 63, owg = tid >> 6;

    if (oh0 >= vl) {
#pragma unroll
        for (int r = 0; r < 4; r++) {
            float* dst = &g_x1[(((size_t)b * 1024 + oh0 + r) * 40) * 64 + c];
#pragma unroll
            for (int q = 0; q < 10; q++) dst[(size_t)(owg * 10 + q) * 64] = 0.f;
        }
        return;
    }

    for (int i = tid; i < 576; i += 256) { sw1[i] = w1[i]; sw2[i] = w2[i]; }
    if (tid < 64) { sb[tid] = b1[tid]; sb[64 + tid] = b2[tid]; }
    for (int i = tid; i < 720; i += 256) {
        int r = i / 80, w = i - r * 80;
        int h = 2 * oh0 + r;
        sin_[r][w] = (h < 2048) ? in[((size_t)b * 2048 + h) * 80 + w] : 0.f;
    }
    __syncthreads();

#pragma unroll
    for (int r = 0; r < 4; r++) {
        int oh = oh0 + r;
        float* dst = &g_x1[(((size_t)b * 1024 + oh) * 40) * 64 + c];
        if (oh < vl) {
#pragma unroll
            for (int q = 0; q < 10; q++) {
                int ow = owg * 10 + q;
                float a1 = sb[c], a2 = sb[64 + c];
#pragma unroll
                for (int kh = 0; kh < 3; kh++)
#pragma unroll
                    for (int kw = 0; kw < 3; kw++) {
                        int w_in = 2 * ow + kw;
                        if (w_in < 80) {
                            float v = sin_[2 * r + kh][w_in];
                            int wi = (kh * 3 + kw) * 64 + c;
                            a1 = fmaf(v, sw1[wi], a1);
                            a2 = fmaf(v, sw2[wi], a2);
                        }
                    }
                dst[(size_t)ow * 64] = fmaxf(a1, a2);
            }
        } else {
#pragma unroll
            for (int q = 0; q < 10; q++) dst[(size_t)(owg * 10 + q) * 64] = 0.f;
        }
    }
}

// ---------------- K2: conv1 maxout — 128 threads, 2 rows x 10 cols/thread ----------------
__global__ void __launch_bounds__(128, 3) k_conv1(
    const float* __restrict__ b1, const float* __restrict__ b2,
    const int* __restrict__ lens)
{
    extern __shared__ float sin_[];  // 5 rows * 40 * 64 floats (51.2KB)
    int tid = threadIdx.x;
    int b   = blockIdx.x >> 8;
    int ohp = blockIdx.x & 255;

    int vl = (lens[b] + 3) >> 2;
    int oc = tid & 63;
    int wq = tid >> 6;            // 0..1 -> 10 ow each

    if (2 * ohp >= vl) {
#pragma unroll
        for (int r = 0; r < 2; r++) {
            int oh = 2 * ohp + r;
#pragma unroll
            for (int q = 0; q < 10; q++) {
                int ow = wq * 10 + q;
                g_x2[(((size_t)b * 512 + oh) * 20 + ow) * 64 + oc] = 0.f;
            }
        }
        return;
    }

    for (int i = tid; i < 12800; i += 128) {
        int r = i / 2560, rem = i - r * 2560;
        int h = 4 * ohp + r;
        sin_[i] = (h < 1024) ? g_x1[((size_t)b * 1024 + h) * 2560 + rem] : 0.f;
    }
    __syncthreads();

    unsigned long long acc1[2][10], acc2[2][10];
    {
        float bb1 = b1[oc], bb2 = b2[oc];
#pragma unroll
        for (int r = 0; r < 2; r++)
#pragma unroll
            for (int q = 0; q < 10; q++) {
                acc1[r][q] = pack2(bb1, 0.f);
                acc2[r][q] = pack2(bb2, 0.f);
            }
    }

#pragma unroll
    for (int kh = 0; kh < 3; kh++) {
#pragma unroll
        for (int kw = 0; kw < 3; kw++) {
            int khkw = kh * 3 + kw;
            const ulonglong2* wr1 = g_wq1 + (size_t)khkw * 1024 + oc;
            const ulonglong2* wr2 = g_wq2 + (size_t)khkw * 1024 + oc;
            int colo[10];
#pragma unroll
            for (int q = 0; q < 10; q++) {
                int w_in = 2 * (wq * 10 + q) + kw;
                colo[q] = (w_in < 40) ? w_in * 64 : -1;
            }
            int rowbase0 = kh * 2560;
            int rowbase1 = (2 + kh) * 2560;
#pragma unroll 2
            for (int ic4 = 0; ic4 < 16; ic4++) {
                ulonglong2 wp1 = wr1[ic4 * 64];
                ulonglong2 wp2 = wr2[ic4 * 64];
#pragma unroll
                for (int q = 0; q < 10; q++) {
                    if (colo[q] >= 0) {
                        int base = colo[q] + ic4 * 4;
                        ulonglong2 v0 = *reinterpret_cast<const ulonglong2*>(&sin_[rowbase0 + base]);
                        ulonglong2 v1 = *reinterpret_cast<const ulonglong2*>(&sin_[rowbase1 + base]);
                        fma2(acc1[0][q], v0.x, wp1.x);
                        fma2(acc1[0][q], v0.y, wp1.y);
                        fma2(acc2[0][q], v0.x, wp2.x);
                        fma2(acc2[0][q], v0.y, wp2.y);
                        fma2(acc1[1][q], v1.x, wp1.x);
                        fma2(acc1[1][q], v1.y, wp1.y);
                        fma2(acc2[1][q], v1.x, wp2.x);
                        fma2(acc2[1][q], v1.y, wp2.y);
                    }
                }
            }
        }
    }

#pragma unroll
    for (int r = 0; r < 2; r++) {
        int oh = 2 * ohp + r;
        float mask = (oh < vl) ? 1.f : 0.f;
#pragma unroll
        for (int q = 0; q < 10; q++) {
            float2 f1 = unpack2(acc1[r][q]);
            float2 f2 = unpack2(acc2[r][q]);
            int ow = wq * 10 + q;
            g_x2[(((size_t)b * 512 + oh) * 20 + ow) * 64 + oc] =
                fmaxf(f1.x + f1.y, f2.x + f2.y) * mask;
        }
    }
}

// ---------------- K3a: projection (packed k-pairs, 4 accumulator chains) ----------------
__global__ void __launch_bounds__(256) k_proj(const float* __restrict__ pb)
{
    __shared__ float sx[8 * 1280];
    int tid = threadIdx.x;
    int b  = blockIdx.x >> 6;
    int s0 = (blockIdx.x & 63) << 3;
    const float* src = &g_x2[((size_t)b * 512 + s0) * 1280];
    for (int i = tid; i < 10240; i += 256) sx[i] = src[i];
    __syncthreads();

    int col = tid & 31, sl = tid >> 5;
    unsigned long long acc[4];
    acc[0] = pack2(pb[col], 0.f);
    acc[1] = 0; acc[2] = 0; acc[3] = 0;
    const float* xr = &sx[sl * 1280];
    const unsigned long long* wp = g_pwp + col;
#pragma unroll 4
    for (int q = 0; q < 640; q += 4) {
#pragma unroll
        for (int j = 0; j < 4; j++) {
            unsigned long long xv =
                *reinterpret_cast<const unsigned long long*>(&xr[2 * (q + j)]);
            fma2(acc[j], xv, wp[(q + j) * 32]);
        }
    }
    float2 f0 = unpack2(acc[0]), f1 = unpack2(acc[1]);
    float2 f2 = unpack2(acc[2]), f3 = unpack2(acc[3]);
    g_p[((size_t)b * 512 + s0 + sl) * 32 + col] =
        (f0.x + f0.y) + (f1.x + f1.y) + (f2.x + f2.y) + (f3.x + f3.y);
}

// ---------------- K3b: encoder conv maxout + mask + squash + layernorm ----------------
__global__ void __launch_bounds__(256) k_enc(
    const float* __restrict__ ew1, const float* __restrict__ eb1,
    const float* __restrict__ ew2, const float* __restrict__ eb2,
    const int* __restrict__ lens)
{
    __shared__ float sp[3][32];
    __shared__ float sw[2][9][8];
    __shared__ float sbb[16];
    int tid = threadIdx.x;
    int p = blockIdx.x;
    int b = p >> 9, s = p & 511;

    if (tid < 96) {
        int j = tid >> 5, ii = tid & 31;
        int si = s + j - 1;
        sp[j][ii] = ((unsigned)si < 512u) ? g_p[((size_t)b * 512 + si) * 32 + ii] : 0.f;
    }
    if (tid < 72) { sw[0][tid / 8][tid & 7] = ew1[tid]; sw[1][tid / 8][tid & 7] = ew2[tid]; }
    if (tid < 16) sbb[tid] = (tid < 8) ? eb1[tid] : eb2[tid - 8];
    __syncthreads();

    int i = tid >> 3, d = tid & 7;
    float a1 = sbb[d], a2 = sbb[8 + d];
#pragma unroll
    for (int kh = 0; kh < 3; kh++)
#pragma unroll
        for (int kw = 0; kw < 3; kw++) {
            int ii = i + kw - 1;
            if ((unsigned)ii < 32u) {
                float v = sp[kh][ii];
                a1 = fmaf(v, sw[0][kh * 3 + kw][d], a1);
                a2 = fmaf(v, sw[1][kh * 3 + kw][d], a2);
            }
        }
    float e = fmaxf(a1, a2);
    int vl = (lens[b] + 3) >> 2;
    if (s >= vl) e = 0.f;

    float sq = e * e;
    sq += __shfl_xor_sync(0xffffffffu, sq, 1);
    sq += __shfl_xor_sync(0xffffffffu, sq, 2);
    sq += __shfl_xor_sync(0xffffffffu, sq, 4);
    float es = e * (sq / (1.f + sq) * rsqrtf(sq + 1e-6f));

    float a = es, b2 = es * es;
    blockReduceSum2(a, b2);
    float mu = a * (1.f / 256.f);
    float var = b2 * (1.f / 256.f) - mu * mu;
    g_emb[(size_t)p * 256 + tid] = (es - mu) * rsqrtf(var + 1e-3f);
}

// ---------------- K4a: u_hat GEMM -> fp16 (chunked; double-buffered; deep-tile skip) ---
template <int LAYER>
__global__ void __launch_bounds__(256) k_uhat(const float* __restrict__ Wt,
                                              const float* __restrict__ Bt,
                                              int pos_base, int buf,
                                              const int* __restrict__ lens)
{
    constexpr int O_REAL = LAYER ? 31 : 32;
    __shared__ float sW[64 * 32];
    __shared__ float sB[8 * 32];
    __shared__ float sWin[64 * 8];
    const float* src = LAYER ? g_emb2 : g_emb;

    int tid = threadIdx.x;
    int i = blockIdx.y;
    int p0 = blockIdx.x * 64;

    {   // deep-tile skip
        int posf = pos_base + p0;
        int bb = posf >> 9, s0 = posf & 511;
        int vl = (lens[bb] + 3) >> 2;
        if (LAYER == 0) {
            if (s0 >= vl + 1) return;
        } else {
            if (s0 >= vl + 2 && s0 + 63 <= 510) return;
        }
    }

    if (O_REAL < 32) {
        for (int t = tid; t < 64 * 32; t += 256) sW[t] = 0.f;
        sB[tid] = 0.f;
        __syncthreads();
    }
    for (int t = tid; t < O_REAL * 64; t += 256) {
        int o = t >> 6, dk = t & 63;
        sW[dk * 32 + o] = Wt[((size_t)i * O_REAL + o) * 64 + dk];
    }
    for (int t = tid; t < O_REAL * 8; t += 256) {
        int o = t >> 3, d = t & 7;
        sB[d * 32 + o] = Bt[((size_t)i * O_REAL + o) * 8 + d];
    }
    {
        int j = i >> 5, ii = i & 31;
        for (int t = tid; t < 512; t += 256) {
            int pl = t >> 3, k = t & 7;
            int pos = pos_base + p0 + pl;
            int b = pos >> 9, s = pos & 511;
            int sn = s + j - 1;
            sWin[t] = ((unsigned)sn < 512u)
                    ? src[(((size_t)b * 512 + sn) * 32 + ii) * 8 + k] : 0.f;
        }
    }
    __syncthreads();

    int o = tid & 31, grp = tid >> 5;
    float Wr[64];
#pragma unroll
    for (int dk = 0; dk < 64; dk++) Wr[dk] = sW[dk * 32 + o];
    float Br[8];
#pragma unroll
    for (int d = 0; d < 8; d++) Br[d] = sB[d * 32 + o];

    uint4* ub = g_ubuf[buf];
#pragma unroll
    for (int ps = 0; ps < 8; ps++) {
        int pl = grp * 8 + ps;
        float wk[8];
        *reinterpret_cast<float4*>(&wk[0]) = *reinterpret_cast<const float4*>(&sWin[pl * 8]);
        *reinterpret_cast<float4*>(&wk[4]) = *reinterpret_cast<const float4*>(&sWin[pl * 8 + 4]);
        float acc[8];
#pragma unroll
        for (int d = 0; d < 8; d++) {
            float a = Br[d];
#pragma unroll
            for (int k = 0; k < 8; k++) a = fmaf(Wr[d * 8 + k], wk[k], a);
            acc[d] = a;
        }
        size_t posl = (size_t)(p0 + pl);
        uint4 uv;
        uv.x = f2h(acc[0], acc[1]);
        uv.y = f2h(acc[2], acc[3]);
        uv.z = f2h(acc[4], acc[5]);
        uv.w = f2h(acc[6], acc[7]);
        ub[(posl * 96 + i) * 32 + o] = uv;
    }
}

// ---------------- K4b: dynamic routing (u fp16 in registers; deep-const fast path) ----
template <int LAYER>
__global__ void __launch_bounds__(256) k_route(float* __restrict__ out_final,
                                               int pos_base, int buf,
                                               const int* __restrict__ lens)
{
    constexpr int O_REAL = LAYER ? 31 : 32;
    __shared__ float sred[8 * 256];
    __shared__ float sv[256];
    __shared__ float slen[32];

    int tid = threadIdx.x;
    int pl = blockIdx.x;
    int p  = pos_base + pl;
    int bb = p >> 9, s = p & 511;
    int vl = (lens[bb] + 3) >> 2;

    if (LAYER == 0) {
        if (s >= vl + 1) {
            g_emb2[(size_t)p * 256 + tid] = g_ec[tid];
            return;
        }
    } else {
        if (s >= vl + 2 && s <= 510) {
            if (tid < 31) out_final[(size_t)p * 31 + tid] = g_outc[tid];
            return;
        }
    }

    int w = tid >> 5, o = tid & 31;

    unsigned uh[12][4];
    float bij[12];
    const uint4* up = &g_ubuf[buf][(((size_t)pl * 96 + w * 12) * 32 + o)];
#pragma unroll
    for (int jj = 0; jj < 12; jj++) {
        uint4 uv = up[jj * 32];
        uh[jj][0] = uv.x; uh[jj][1] = uv.y; uh[jj][2] = uv.z; uh[jj][3] = uv.w;
        bij[jj] = 0.f;
    }

    float mask = 0.f;
    if (LAYER == 1) { if (o == 0 || o >= O_REAL) mask = -1e9f; }

    int oo = tid >> 3, dd = tid & 7;
    float v_od = 0.f;

    for (int it = 0; it < 3; it++) {
        float sp8[8] = {0, 0, 0, 0, 0, 0, 0, 0};
#pragma unroll
        for (int jj = 0; jj < 12; jj++) {
            float e = __expf(bij[jj] + mask);
            float ssum = e;
#pragma unroll
            for (int off = 16; off; off >>= 1)
                ssum += __shfl_xor_sync(0xffffffffu, ssum, off);
            float c = __fdividef(e, ssum);
#pragma unroll
            for (int t = 0; t < 4; t++) {
                float2 f = h2f(uh[jj][t]);
                sp8[2 * t]     = fmaf(c, f.x, sp8[2 * t]);
                sp8[2 * t + 1] = fmaf(c, f.y, sp8[2 * t + 1]);
            }
        }
        *reinterpret_cast<float4*>(&sred[w * 256 + o * 8]) =
            make_float4(sp8[0], sp8[1], sp8[2], sp8[3]);
        *reinterpret_cast<float4*>(&sred[w * 256 + o * 8 + 4]) =
            make_float4(sp8[4], sp8[5], sp8[6], sp8[7]);
        __syncthreads();

        float s_od = 0.f;
#pragma unroll
        for (int w2 = 0; w2 < 8; w2++) s_od += sred[w2 * 256 + tid];
        float sq = s_od * s_od;
        sq += __shfl_xor_sync(0xffffffffu, sq, 1);
        sq += __shfl_xor_sync(0xffffffffu, sq, 2);
        sq += __shfl_xor_sync(0xffffffffu, sq, 4);
        v_od = s_od * (sq / (1.f + sq) * rsqrtf(sq + 1e-6f));
        sv[tid] = v_od;
        __syncthreads();

        if (it < 2) {
            float vv[8];
            *reinterpret_cast<float4*>(&vv[0]) = *reinterpret_cast<const float4*>(&sv[o * 8]);
            *reinterpret_cast<float4*>(&vv[4]) = *reinterpret_cast<const float4*>(&sv[o * 8 + 4]);
#pragma unroll
            for (int jj = 0; jj < 12; jj++) {
                float acc = 0.f;
#pragma unroll
                for (int t = 0; t < 4; t++) {
                    float2 f = h2f(uh[jj][t]);
                    acc = fmaf(f.x, vv[2 * t], acc);
                    acc = fmaf(f.y, vv[2 * t + 1], acc);
                }
                bij[jj] += acc;
            }
        }
    }

    if (LAYER == 0) {
        float a = v_od, b2 = v_od * v_od;
        blockReduceSum2(a, b2);
        float mu = a * (1.f / 256.f);
        float var = b2 * (1.f / 256.f) - mu * mu;
        g_emb2[(size_t)p * 256 + tid] = (v_od - mu) * rsqrtf(var + 1e-3f);
    } else {
        bool valid = (oo < O_REAL);
        float x = valid ? v_od : 0.f;
        float a = x, b2 = x * x;
        blockReduceSum2(a, b2);
        const float inv = 1.f / (float)(O_REAL * 8);
        float mu = a * inv;
        float var = b2 * inv - mu * mu;
        float vn = valid ? (x - mu) * rsqrtf(var + 1e-3f) : 0.f;
        float sq = vn * vn;
        sq += __shfl_xor_sync(0xffffffffu, sq, 1);
        sq += __shfl_xor_sync(0xffffffffu, sq, 2);
        sq += __shfl_xor_sync(0xffffffffu, sq, 4);
        if (dd == 0) slen[oo] = sqrtf(sq + 1e-6f);
        __syncthreads();
        if (tid < 32) {
            float l = (tid < O_REAL) ? slen[tid] : 0.f;
            float sa = l, sb = l * l;
#pragma unroll
            for (int off = 16; off; off >>= 1) {
                sa += __shfl_xor_sync(0xffffffffu, sa, off);
                sb += __shfl_xor_sync(0xffffffffu, sb, off);
            }
            float mu2 = sa / 31.f;
            float var2 = sb / 31.f - mu2 * mu2;
            if (tid < 31)
                out_final[(size_t)p * 31 + tid] = (l - mu2) * rsqrtf(var2 + 1e-3f);
        }
    }
}

// ---------------- launch ----------------
extern "C" void kernel_launch(void* const* d_in, const int* in_sizes, int n_in,
                              void* d_out, int out_size)
{
    (void)in_sizes; (void)n_in; (void)out_size;
    const float* inputs = (const float*)d_in[0];
    const float* c0w1 = (const float*)d_in[1];
    const float* c0b1 = (const float*)d_in[2];
    const float* c0w2 = (const float*)d_in[3];
    const float* c0b2 = (const float*)d_in[4];
    const float* c1w1 = (const float*)d_in[5];
    const float* c1b1 = (const float*)d_in[6];
    const float* c1w2 = (const float*)d_in[7];
    const float* c1b2 = (const float*)d_in[8];
    const float* pw   = (const float*)d_in[9];
    const float* pb   = (const float*)d_in[10];
    const float* ew1  = (const float*)d_in[11];
    const float* eb1  = (const float*)d_in[12];
    const float* ew2  = (const float*)d_in[13];
    const float* eb2  = (const float*)d_in[14];
    const float* W0   = (const float*)d_in[15];
    const float* B0   = (const float*)d_in[16];
    const float* W1   = (const float*)d_in[17];
    const float* B1   = (const float*)d_in[18];
    const int*   lens = (const int*)d_in[19];
    float* out = (float*)d_out;

    static cudaStream_t s2 = nullptr;
    static cudaEvent_t evStart = nullptr, evFork = nullptr, evJoin = nullptr, evC = nullptr;
    if (!s2) {
        cudaStreamCreateWithFlags(&s2, cudaStreamNonBlocking);
        cudaEventCreateWithFlags(&evStart, cudaEventDisableTiming);
        cudaEventCreateWithFlags(&evFork, cudaEventDisableTiming);
        cudaEventCreateWithFlags(&evJoin, cudaEventDisableTiming);
        cudaEventCreateWithFlags(&evC, cudaEventDisableTiming);
        cudaFuncSetAttribute(k_conv1, cudaFuncAttributeMaxDynamicSharedMemorySize, 52224);
    }

    // fork s2 into the capture graph FIRST, then k_const on s2
    cudaEventRecord(evStart, 0);
    cudaStreamWaitEvent(s2, evStart, 0);
    k_const<<<1, 256, 0, s2>>>(B0, W1, B1);
    cudaEventRecord(evC, s2);

    // head pipeline on stream 0
    k_prep<<<116, 256>>>(c1w1, c1w2, pw);
    k_conv0<<<2048, 256>>>(inputs, c0w1, c0b1, c0w2, c0b2, lens);
    k_conv1<<<2048, 128, 52224>>>(c1b1, c1b2, lens);
    k_proj<<<512, 256>>>(pb);
    k_enc<<<4096, 256>>>(ew1, eb1, ew2, eb2, lens);

    // fork: s2 waits for head pipeline; stream 0 waits for k_const
    cudaEventRecord(evFork, 0);
    cudaStreamWaitEvent(s2, evFork, 0);
    cudaStreamWaitEvent(0, evC, 0);

    // two independent chunk chains (one per stream), CHUNK=2048
    for (int c = 0; c < NCHUNK; c++) {
        int base = c * CHUNK;
        int buf = c & 1;
        cudaStream_t st = (c & 1) ? s2 : (cudaStream_t)0;
        k_uhat<0><<<dim3(CHUNK / 64, 96), 256, 0, st>>>(W0, B0, base, buf, lens);
        k_route<0><<<CHUNK, 256, 0, st>>>(nullptr, base, buf, lens);
        k_uhat<1><<<dim3(CHUNK / 64, 96), 256, 0, st>>>(W1, B1, base, buf, lens);
        k_route<1><<<CHUNK, 256, 0, st>>>(out, base, buf, lens);
    }

    // join
    cudaEventRecord(evJoin, s2);
    cudaStreamWaitEvent(0, evJoin, 0);
}

// round 15
// speedup vs baseline: 1.1453x; 1.1453x over previous
#include <cuda_runtime.h>
#include <cuda_bf16.h>
#include <cuda_fp16.h>
#include <cstdint>

// ---------------- scratch (device globals; no runtime allocation) ----------------
__device__ float g_x1[(size_t)8 * 1024 * 40 * 64];   // conv0 out [B,1024,40,64]
__device__ float g_x2[(size_t)8 * 512 * 20 * 64];    // conv1 out [B,512,20,64]
__device__ float g_p [(size_t)4096 * 32];            // proj out  [B*S,32]
__device__ float g_emb [(size_t)4096 * 256];         // primary caps [B*S,32,8]
__device__ float g_emb2[(size_t)4096 * 256];         // conv caps    [B*S,32,8]
__device__ uint4 g_ubuf[2][(size_t)1024 * 96 * 32];  // u_hat fp16 double buffer (2x50MB, L2-resident)
__device__ ulonglong2 g_wq1[9 * 16 * 64];            // conv1 w1 packed (ic quads, 2x f32x2)
__device__ ulonglong2 g_wq2[9 * 16 * 64];            // conv1 w2 packed
__device__ unsigned long long g_pwp[640 * 32];       // proj w packed (k pairs)
__device__ float g_ec[256];                          // layer-0 bias-routing constant (post-LN)
__device__ float g_outc[31];                         // layer-1 bias-routing constant (final)

#define CHUNK 1024
#define NCHUNK 4

// ---------------- helpers ----------------
__device__ __forceinline__ unsigned long long pack2(float x, float y) {
    unsigned long long r;
    asm("mov.b64 %0, {%1, %2};" : "=l"(r) : "f"(x), "f"(y));
    return r;
}
__device__ __forceinline__ void fma2(unsigned long long& c, unsigned long long a, unsigned long long b) {
    asm("fma.rn.f32x2 %0, %1, %2, %0;" : "+l"(c) : "l"(a), "l"(b));
}
__device__ __forceinline__ float2 unpack2(unsigned long long v) {
    float lo, hi;
    asm("mov.b64 {%0, %1}, %2;" : "=f"(lo), "=f"(hi) : "l"(v));
    return make_float2(lo, hi);
}
__device__ __forceinline__ float2 h2f(unsigned u) {
    __half2 h = *reinterpret_cast<__half2*>(&u);
    return __half22float2(h);
}
__device__ __forceinline__ unsigned f2h(float a, float b) {
    __half2 h = __floats2half2_rn(a, b);
    return *reinterpret_cast<unsigned*>(&h);
}

__device__ __forceinline__ void blockReduceSum2(float& a, float& b) {
    __shared__ float red[16];
    int lane = threadIdx.x & 31, w = threadIdx.x >> 5;
#pragma unroll
    for (int o = 16; o; o >>= 1) {
        a += __shfl_xor_sync(0xffffffffu, a, o);
        b += __shfl_xor_sync(0xffffffffu, b, o);
    }
    if (lane == 0) { red[w] = a; red[8 + w] = b; }
    __syncthreads();
    a = red[0] + red[1] + red[2] + red[3] + red[4] + red[5] + red[6] + red[7];
    b = red[8] + red[9] + red[10] + red[11] + red[12] + red[13] + red[14] + red[15];
    __syncthreads();
}

// shared routing core: u in fp32 registers, softmax over o = lanes.
// c0 = exact iteration-0 coupling coefficient (softmax of all-zero logits).
__device__ __forceinline__ float route_core(float (&uj)[12][8], float mask, float c0,
                                            float* sred, float* sv, int tid)
{
    int w = tid >> 5, o = tid & 31;
    float bij[12];
#pragma unroll
    for (int jj = 0; jj < 12; jj++) bij[jj] = 0.f;
    float v_od = 0.f;
    for (int it = 0; it < 3; it++) {
        float sp8[8] = {0, 0, 0, 0, 0, 0, 0, 0};
        if (it == 0) {
            // bij == 0 everywhere -> coupling is the constant c0 (exact)
#pragma unroll
            for (int jj = 0; jj < 12; jj++)
#pragma unroll
                for (int d = 0; d < 8; d++) sp8[d] = fmaf(c0, uj[jj][d], sp8[d]);
        } else {
#pragma unroll
            for (int jj = 0; jj < 12; jj++) {
                float e = __expf(bij[jj] + mask);
                float ssum = e;
#pragma unroll
                for (int off = 16; off; off >>= 1)
                    ssum += __shfl_xor_sync(0xffffffffu, ssum, off);
                float c = __fdividef(e, ssum);
#pragma unroll
                for (int d = 0; d < 8; d++) sp8[d] = fmaf(c, uj[jj][d], sp8[d]);
            }
        }
        *reinterpret_cast<float4*>(&sred[w * 256 + o * 8]) =
            make_float4(sp8[0], sp8[1], sp8[2], sp8[3]);
        *reinterpret_cast<float4*>(&sred[w * 256 + o * 8 + 4]) =
            make_float4(sp8[4], sp8[5], sp8[6], sp8[7]);
        __syncthreads();
        float s_od = 0.f;
#pragma unroll
        for (int w2 = 0; w2 < 8; w2++) s_od += sred[w2 * 256 + tid];
        float sq = s_od * s_od;
        sq += __shfl_xor_sync(0xffffffffu, sq, 1);
        sq += __shfl_xor_sync(0xffffffffu, sq, 2);
        sq += __shfl_xor_sync(0xffffffffu, sq, 4);
        v_od = s_od * (sq / (1.f + sq) * rsqrtf(sq + 1e-6f));
        sv[tid] = v_od;
        __syncthreads();
        if (it < 2) {
            float vv[8];
            *reinterpret_cast<float4*>(&vv[0]) = *reinterpret_cast<const float4*>(&sv[o * 8]);
            *reinterpret_cast<float4*>(&vv[4]) = *reinterpret_cast<const float4*>(&sv[o * 8 + 4]);
#pragma unroll
            for (int jj = 0; jj < 12; jj++) {
                float acc = 0.f;
#pragma unroll
                for (int d = 0; d < 8; d++) acc = fmaf(uj[jj][d], vv[d], acc);
                bij[jj] += acc;
            }
        }
    }
    return v_od;
}

// ---------------- K0: weight pre-packing ----------------
__global__ void __launch_bounds__(256) k_prep(const float* __restrict__ w1,
                                              const float* __restrict__ w2,
                                              const float* __restrict__ pw)
{
    int idx = blockIdx.x * 256 + threadIdx.x;
    if (idx < 9 * 16 * 64) {
        int oc = idx & 63, r = idx >> 6;
        int khkw = r >> 4, ic4 = r & 15;
        int base = (khkw * 64 + ic4 * 4) * 64 + oc;
        ulonglong2 v1, v2;
        v1.x = pack2(w1[base], w1[base + 64]);
        v1.y = pack2(w1[base + 128], w1[base + 192]);
        v2.x = pack2(w2[base], w2[base + 64]);
        v2.y = pack2(w2[base + 128], w2[base + 192]);
        g_wq1[idx] = v1;
        g_wq2[idx] = v2;
    }
    int pidx = idx - 9 * 16 * 64;
    if (pidx >= 0 && pidx < 640 * 32) {
        int col = pidx & 31, q = pidx >> 5;
        g_pwp[pidx] = pack2(pw[(2 * q) * 32 + col], pw[(2 * q + 1) * 32 + col]);
    }
}

// ---------------- K0b: bias-only routing constants (1 block) ----------------
__global__ void __launch_bounds__(256) k_const(const float* __restrict__ B0,
                                               const float* __restrict__ W1,
                                               const float* __restrict__ B1)
{
    __shared__ float sred[8 * 256];
    __shared__ float sv[256];
    __shared__ float sec[256];
    __shared__ float slen[32];
    int tid = threadIdx.x;
    int w = tid >> 5, o = tid & 31;

    float uj[12][8];
#pragma unroll
    for (int jj = 0; jj < 12; jj++)
#pragma unroll
        for (int d = 0; d < 8; d++)
            uj[jj][d] = B0[(((size_t)(w * 12 + jj) * 32) + o) * 8 + d];

    float v_od = route_core(uj, 0.f, 1.f / 32.f, sred, sv, tid);

    float a = v_od, b2 = v_od * v_od;
    blockReduceSum2(a, b2);
    float mu = a * (1.f / 256.f);
    float var = b2 * (1.f / 256.f) - mu * mu;
    float ec = (v_od - mu) * rsqrtf(var + 1e-3f);
    sec[tid] = ec;
    g_ec[tid] = ec;
    __syncthreads();

    float uj2[12][8];
#pragma unroll
    for (int jj = 0; jj < 12; jj++) {
        int i = w * 12 + jj, ii = i & 31;
#pragma unroll
        for (int d = 0; d < 8; d++) {
            float acc = 0.f;
            if (o < 31) {
                acc = B1[((size_t)i * 31 + o) * 8 + d];
                const float* Wr = &W1[(((size_t)i * 31 + o) * 8 + d) * 8];
#pragma unroll
                for (int k = 0; k < 8; k++) acc = fmaf(Wr[k], sec[ii * 8 + k], acc);
            }
            uj2[jj][d] = acc;
        }
    }
    __syncthreads();
    bool masked1 = (o == 0 || o >= 31);
    float mask = masked1 ? -1e9f : 0.f;
    float c01 = masked1 ? 0.f : (1.f / 30.f);
    v_od = route_core(uj2, mask, c01, sred, sv, tid);

    int oo = tid >> 3, dd = tid & 7;
    bool valid = (oo < 31);
    float x = valid ? v_od : 0.f;
    a = x; b2 = x * x;
    blockReduceSum2(a, b2);
    mu = a * (1.f / 248.f);
    var = b2 * (1.f / 248.f) - mu * mu;
    float vn = valid ? (x - mu) * rsqrtf(var + 1e-3f) : 0.f;
    float sq = vn * vn;
    sq += __shfl_xor_sync(0xffffffffu, sq, 1);
    sq += __shfl_xor_sync(0xffffffffu, sq, 2);
    sq += __shfl_xor_sync(0xffffffffu, sq, 4);
    if (dd == 0) slen[oo] = sqrtf(sq + 1e-6f);
    __syncthreads();
    if (tid < 32) {
        float l = (tid < 31) ? slen[tid] : 0.f;
        float sa = l, sb = l * l;
#pragma unroll
        for (int off = 16; off; off >>= 1) {
            sa += __shfl_xor_sync(0xffffffffu, sa, off);
            sb += __shfl_xor_sync(0xffffffffu, sb, off);
        }
        float mu2 = sa / 31.f;
        float var2 = sb / 31.f - mu2 * mu2;
        if (tid < 31) g_outc[tid] = (l - mu2) * rsqrtf(var2 + 1e-3f);
    }
}

// ---------------- K1: conv0 maxout + time mask (4 output rows per block) ----------------
__global__ void __launch_bounds__(256) k_conv0(
    const float* __restrict__ in,
    const float* __restrict__ w1, const float* __restrict__ b1,
    const float* __restrict__ w2, const float* __restrict__ b2,
    const int* __restrict__ lens)
{
    __shared__ float sw1[576], sw2[576], sb[128];
    __shared__ float sin_[9][80];
    int tid = threadIdx.x;
    int b   = blockIdx.x >> 8;
    int oh0 = (blockIdx.x & 255) << 2;
    int vl = (lens[b] + 1) >> 1;
    int c = tid & 63, owg = tid >> 6;

    if (oh0 >= vl) {
#pragma unroll
        for (int r = 0; r < 4; r++) {
            float* dst = &g_x1[(((size_t)b * 1024 + oh0 + r) * 40) * 64 + c];
#pragma unroll
            for (int q = 0; q < 10; q++) dst[(size_t)(owg * 10 + q) * 64] = 0.f;
        }
        return;
    }

    for (int i = tid; i < 576; i += 256) { sw1[i] = w1[i]; sw2[i] = w2[i]; }
    if (tid < 64) { sb[tid] = b1[tid]; sb[64 + tid] = b2[tid]; }
    for (int i = tid; i < 720; i += 256) {
        int r = i / 80, w = i - r * 80;
        int h = 2 * oh0 + r;
        sin_[r][w] = (h < 2048) ? in[((size_t)b * 2048 + h) * 80 + w] : 0.f;
    }
    __syncthreads();

#pragma unroll
    for (int r = 0; r < 4; r++) {
        int oh = oh0 + r;
        float* dst = &g_x1[(((size_t)b * 1024 + oh) * 40) * 64 + c];
        if (oh < vl) {
#pragma unroll
            for (int q = 0; q < 10; q++) {
                int ow = owg * 10 + q;
                float a1 = sb[c], a2 = sb[64 + c];
#pragma unroll
                for (int kh = 0; kh < 3; kh++)
#pragma unroll
                    for (int kw = 0; kw < 3; kw++) {
                        int w_in = 2 * ow + kw;
                        if (w_in < 80) {
                            float v = sin_[2 * r + kh][w_in];
                            int wi = (kh * 3 + kw) * 64 + c;
                            a1 = fmaf(v, sw1[wi], a1);
                            a2 = fmaf(v, sw2[wi], a2);
                        }
                    }
                dst[(size_t)ow * 64] = fmaxf(a1, a2);
            }
        } else {
#pragma unroll
            for (int q = 0; q < 10; q++) dst[(size_t)(owg * 10 + q) * 64] = 0.f;
        }
    }
}

// ---------------- K2: conv1 maxout — 128 threads, 2 rows x 10 cols/thread ----------------
__global__ void __launch_bounds__(128, 3) k_conv1(
    const float* __restrict__ b1, const float* __restrict__ b2,
    const int* __restrict__ lens)
{
    extern __shared__ float sin_[];  // 5 rows * 40 * 64 floats (51.2KB)
    int tid = threadIdx.x;
    int b   = blockIdx.x >> 8;
    int ohp = blockIdx.x & 255;

    int vl = (lens[b] + 3) >> 2;
    int oc = tid & 63;
    int wq = tid >> 6;            // 0..1 -> 10 ow each

    if (2 * ohp >= vl) {
#pragma unroll
        for (int r = 0; r < 2; r++) {
            int oh = 2 * ohp + r;
#pragma unroll
            for (int q = 0; q < 10; q++) {
                int ow = wq * 10 + q;
                g_x2[(((size_t)b * 512 + oh) * 20 + ow) * 64 + oc] = 0.f;
            }
        }
        return;
    }

    for (int i = tid; i < 12800; i += 128) {
        int r = i / 2560, rem = i - r * 2560;
        int h = 4 * ohp + r;
        sin_[i] = (h < 1024) ? g_x1[((size_t)b * 1024 + h) * 2560 + rem] : 0.f;
    }
    __syncthreads();

    unsigned long long acc1[2][10], acc2[2][10];
    {
        float bb1 = b1[oc], bb2 = b2[oc];
#pragma unroll
        for (int r = 0; r < 2; r++)
#pragma unroll
            for (int q = 0; q < 10; q++) {
                acc1[r][q] = pack2(bb1, 0.f);
                acc2[r][q] = pack2(bb2, 0.f);
            }
    }

#pragma unroll
    for (int kh = 0; kh < 3; kh++) {
#pragma unroll
        for (int kw = 0; kw < 3; kw++) {
            int khkw = kh * 3 + kw;
            const ulonglong2* wr1 = g_wq1 + (size_t)khkw * 1024 + oc;
            const ulonglong2* wr2 = g_wq2 + (size_t)khkw * 1024 + oc;
            int colo[10];
#pragma unroll
            for (int q = 0; q < 10; q++) {
                int w_in = 2 * (wq * 10 + q) + kw;
                colo[q] = (w_in < 40) ? w_in * 64 : -1;
            }
            int rowbase0 = kh * 2560;
            int rowbase1 = (2 + kh) * 2560;
#pragma unroll 2
            for (int ic4 = 0; ic4 < 16; ic4++) {
                ulonglong2 wp1 = wr1[ic4 * 64];
                ulonglong2 wp2 = wr2[ic4 * 64];
#pragma unroll
                for (int q = 0; q < 10; q++) {
                    if (colo[q] >= 0) {
                        int base = colo[q] + ic4 * 4;
                        ulonglong2 v0 = *reinterpret_cast<const ulonglong2*>(&sin_[rowbase0 + base]);
                        ulonglong2 v1 = *reinterpret_cast<const ulonglong2*>(&sin_[rowbase1 + base]);
                        fma2(acc1[0][q], v0.x, wp1.x);
                        fma2(acc1[0][q], v0.y, wp1.y);
                        fma2(acc2[0][q], v0.x, wp2.x);
                        fma2(acc2[0][q], v0.y, wp2.y);
                        fma2(acc1[1][q], v1.x, wp1.x);
                        fma2(acc1[1][q], v1.y, wp1.y);
                        fma2(acc2[1][q], v1.x, wp2.x);
                        fma2(acc2[1][q], v1.y, wp2.y);
                    }
                }
            }
        }
    }

#pragma unroll
    for (int r = 0; r < 2; r++) {
        int oh = 2 * ohp + r;
        float mask = (oh < vl) ? 1.f : 0.f;
#pragma unroll
        for (int q = 0; q < 10; q++) {
            float2 f1 = unpack2(acc1[r][q]);
            float2 f2 = unpack2(acc2[r][q]);
            int ow = wq * 10 + q;
            g_x2[(((size_t)b * 512 + oh) * 20 + ow) * 64 + oc] =
                fmaxf(f1.x + f1.y, f2.x + f2.y) * mask;
        }
    }
}

// ---------------- K3a: projection (packed k-pairs, 4 accumulator chains) ----------------
__global__ void __launch_bounds__(256) k_proj(const float* __restrict__ pb)
{
    __shared__ float sx[8 * 1280];
    int tid = threadIdx.x;
    int b  = blockIdx.x >> 6;
    int s0 = (blockIdx.x & 63) << 3;
    const float* src = &g_x2[((size_t)b * 512 + s0) * 1280];
    for (int i = tid; i < 10240; i += 256) sx[i] = src[i];
    __syncthreads();

    int col = tid & 31, sl = tid >> 5;
    unsigned long long acc[4];
    acc[0] = pack2(pb[col], 0.f);
    acc[1] = 0; acc[2] = 0; acc[3] = 0;
    const float* xr = &sx[sl * 1280];
    const unsigned long long* wp = g_pwp + col;
#pragma unroll 4
    for (int q = 0; q < 640; q += 4) {
#pragma unroll
        for (int j = 0; j < 4; j++) {
            unsigned long long xv =
                *reinterpret_cast<const unsigned long long*>(&xr[2 * (q + j)]);
            fma2(acc[j], xv, wp[(q + j) * 32]);
        }
    }
    float2 f0 = unpack2(acc[0]), f1 = unpack2(acc[1]);
    float2 f2 = unpack2(acc[2]), f3 = unpack2(acc[3]);
    g_p[((size_t)b * 512 + s0 + sl) * 32 + col] =
        (f0.x + f0.y) + (f1.x + f1.y) + (f2.x + f2.y) + (f3.x + f3.y);
}

// ---------------- K3b: encoder conv maxout + mask + squash + layernorm ----------------
__global__ void __launch_bounds__(256) k_enc(
    const float* __restrict__ ew1, const float* __restrict__ eb1,
    const float* __restrict__ ew2, const float* __restrict__ eb2,
    const int* __restrict__ lens)
{
    __shared__ float sp[3][32];
    __shared__ float sw[2][9][8];
    __shared__ float sbb[16];
    int tid = threadIdx.x;
    int p = blockIdx.x;
    int b = p >> 9, s = p & 511;

    if (tid < 96) {
        int j = tid >> 5, ii = tid & 31;
        int si = s + j - 1;
        sp[j][ii] = ((unsigned)si < 512u) ? g_p[((size_t)b * 512 + si) * 32 + ii] : 0.f;
    }
    if (tid < 72) { sw[0][tid / 8][tid & 7] = ew1[tid]; sw[1][tid / 8][tid & 7] = ew2[tid]; }
    if (tid < 16) sbb[tid] = (tid < 8) ? eb1[tid] : eb2[tid - 8];
    __syncthreads();

    int i = tid >> 3, d = tid & 7;
    float a1 = sbb[d], a2 = sbb[8 + d];
#pragma unroll
    for (int kh = 0; kh < 3; kh++)
#pragma unroll
        for (int kw = 0; kw < 3; kw++) {
            int ii = i + kw - 1;
            if ((unsigned)ii < 32u) {
                float v = sp[kh][ii];
                a1 = fmaf(v, sw[0][kh * 3 + kw][d], a1);
                a2 = fmaf(v, sw[1][kh * 3 + kw][d], a2);
            }
        }
    float e = fmaxf(a1, a2);
    int vl = (lens[b] + 3) >> 2;
    if (s >= vl) e = 0.f;

    float sq = e * e;
    sq += __shfl_xor_sync(0xffffffffu, sq, 1);
    sq += __shfl_xor_sync(0xffffffffu, sq, 2);
    sq += __shfl_xor_sync(0xffffffffu, sq, 4);
    float es = e * (sq / (1.f + sq) * rsqrtf(sq + 1e-6f));

    float a = es, b2 = es * es;
    blockReduceSum2(a, b2);
    float mu = a * (1.f / 256.f);
    float var = b2 * (1.f / 256.f) - mu * mu;
    g_emb[(size_t)p * 256 + tid] = (es - mu) * rsqrtf(var + 1e-3f);
}

// ---------------- K4a: u_hat GEMM -> fp16 (chunked; double-buffered; deep-tile skip) ---
template <int LAYER>
__global__ void __launch_bounds__(256) k_uhat(const float* __restrict__ Wt,
                                              const float* __restrict__ Bt,
                                              int pos_base, int buf,
                                              const int* __restrict__ lens)
{
    constexpr int O_REAL = LAYER ? 31 : 32;
    __shared__ float sW[64 * 32];
    __shared__ float sB[8 * 32];
    __shared__ float sWin[64 * 8];
    const float* src = LAYER ? g_emb2 : g_emb;

    int tid = threadIdx.x;
    int i = blockIdx.y;
    int p0 = blockIdx.x * 64;

    {   // deep-tile skip
        int posf = pos_base + p0;
        int bb = posf >> 9, s0 = posf & 511;
        int vl = (lens[bb] + 3) >> 2;
        if (LAYER == 0) {
            if (s0 >= vl + 1) return;
        } else {
            if (s0 >= vl + 2 && s0 + 63 <= 510) return;
        }
    }

    if (O_REAL < 32) {
        for (int t = tid; t < 64 * 32; t += 256) sW[t] = 0.f;
        sB[tid] = 0.f;
        __syncthreads();
    }
    for (int t = tid; t < O_REAL * 64; t += 256) {
        int o = t >> 6, dk = t & 63;
        sW[dk * 32 + o] = Wt[((size_t)i * O_REAL + o) * 64 + dk];
    }
    for (int t = tid; t < O_REAL * 8; t += 256) {
        int o = t >> 3, d = t & 7;
        sB[d * 32 + o] = Bt[((size_t)i * O_REAL + o) * 8 + d];
    }
    {
        int j = i >> 5, ii = i & 31;
        for (int t = tid; t < 512; t += 256) {
            int pl = t >> 3, k = t & 7;
            int pos = pos_base + p0 + pl;
            int b = pos >> 9, s = pos & 511;
            int sn = s + j - 1;
            sWin[t] = ((unsigned)sn < 512u)
                    ? src[(((size_t)b * 512 + sn) * 32 + ii) * 8 + k] : 0.f;
        }
    }
    __syncthreads();

    int o = tid & 31, grp = tid >> 5;
    float Wr[64];
#pragma unroll
    for (int dk = 0; dk < 64; dk++) Wr[dk] = sW[dk * 32 + o];
    float Br[8];
#pragma unroll
    for (int d = 0; d < 8; d++) Br[d] = sB[d * 32 + o];

    uint4* ub = g_ubuf[buf];
#pragma unroll
    for (int ps = 0; ps < 8; ps++) {
        int pl = grp * 8 + ps;
        float wk[8];
        *reinterpret_cast<float4*>(&wk[0]) = *reinterpret_cast<const float4*>(&sWin[pl * 8]);
        *reinterpret_cast<float4*>(&wk[4]) = *reinterpret_cast<const float4*>(&sWin[pl * 8 + 4]);
        float acc[8];
#pragma unroll
        for (int d = 0; d < 8; d++) {
            float a = Br[d];
#pragma unroll
            for (int k = 0; k < 8; k++) a = fmaf(Wr[d * 8 + k], wk[k], a);
            acc[d] = a;
        }
        size_t posl = (size_t)(p0 + pl);
        uint4 uv;
        uv.x = f2h(acc[0], acc[1]);
        uv.y = f2h(acc[2], acc[3]);
        uv.z = f2h(acc[4], acc[5]);
        uv.w = f2h(acc[6], acc[7]);
        ub[(posl * 96 + i) * 32 + o] = uv;
    }
}

// ---------------- K4b: dynamic routing (u fp16 in registers; deep-const fast path) ----
template <int LAYER>
__global__ void __launch_bounds__(256) k_route(float* __restrict__ out_final,
                                               int pos_base, int buf,
                                               const int* __restrict__ lens)
{
    constexpr int O_REAL = LAYER ? 31 : 32;
    __shared__ float sred[8 * 256];
    __shared__ float sv[256];
    __shared__ float slen[32];

    int tid = threadIdx.x;
    int pl = blockIdx.x;
    int p  = pos_base + pl;
    int bb = p >> 9, s = p & 511;
    int vl = (lens[bb] + 3) >> 2;

    if (LAYER == 0) {
        if (s >= vl + 1) {
            g_emb2[(size_t)p * 256 + tid] = g_ec[tid];
            return;
        }
    } else {
        if (s >= vl + 2 && s <= 510) {
            if (tid < 31) out_final[(size_t)p * 31 + tid] = g_outc[tid];
            return;
        }
    }

    int w = tid >> 5, o = tid & 31;

    unsigned uh[12][4];
    float bij[12];
    const uint4* up = &g_ubuf[buf][(((size_t)pl * 96 + w * 12) * 32 + o)];
#pragma unroll
    for (int jj = 0; jj < 12; jj++) {
        uint4 uv = up[jj * 32];
        uh[jj][0] = uv.x; uh[jj][1] = uv.y; uh[jj][2] = uv.z; uh[jj][3] = uv.w;
        bij[jj] = 0.f;
    }

    bool maskd = (LAYER == 1) && (o == 0 || o >= O_REAL);
    float mask = maskd ? -1e9f : 0.f;
    float c0 = (LAYER == 0) ? (1.f / 32.f) : (maskd ? 0.f : (1.f / 30.f));

    int oo = tid >> 3, dd = tid & 7;
    float v_od = 0.f;

    for (int it = 0; it < 3; it++) {
        float sp8[8] = {0, 0, 0, 0, 0, 0, 0, 0};
        if (it == 0) {
            // iteration-0 coupling is the exact constant c0
#pragma unroll
            for (int jj = 0; jj < 12; jj++)
#pragma unroll
                for (int t = 0; t < 4; t++) {
                    float2 f = h2f(uh[jj][t]);
                    sp8[2 * t]     = fmaf(c0, f.x, sp8[2 * t]);
                    sp8[2 * t + 1] = fmaf(c0, f.y, sp8[2 * t + 1]);
                }
        } else {
#pragma unroll
            for (int jj = 0; jj < 12; jj++) {
                float e = __expf(bij[jj] + mask);
                float ssum = e;
#pragma unroll
                for (int off = 16; off; off >>= 1)
                    ssum += __shfl_xor_sync(0xffffffffu, ssum, off);
                float c = __fdividef(e, ssum);
#pragma unroll
                for (int t = 0; t < 4; t++) {
                    float2 f = h2f(uh[jj][t]);
                    sp8[2 * t]     = fmaf(c, f.x, sp8[2 * t]);
                    sp8[2 * t + 1] = fmaf(c, f.y, sp8[2 * t + 1]);
                }
            }
        }
        *reinterpret_cast<float4*>(&sred[w * 256 + o * 8]) =
            make_float4(sp8[0], sp8[1], sp8[2], sp8[3]);
        *reinterpret_cast<float4*>(&sred[w * 256 + o * 8 + 4]) =
            make_float4(sp8[4], sp8[5], sp8[6], sp8[7]);
        __syncthreads();

        float s_od = 0.f;
#pragma unroll
        for (int w2 = 0; w2 < 8; w2++) s_od += sred[w2 * 256 + tid];
        float sq = s_od * s_od;
        sq += __shfl_xor_sync(0xffffffffu, sq, 1);
        sq += __shfl_xor_sync(0xffffffffu, sq, 2);
        sq += __shfl_xor_sync(0xffffffffu, sq, 4);
        v_od = s_od * (sq / (1.f + sq) * rsqrtf(sq + 1e-6f));
        sv[tid] = v_od;
        __syncthreads();

        if (it < 2) {
            float vv[8];
            *reinterpret_cast<float4*>(&vv[0]) = *reinterpret_cast<const float4*>(&sv[o * 8]);
            *reinterpret_cast<float4*>(&vv[4]) = *reinterpret_cast<const float4*>(&sv[o * 8 + 4]);
#pragma unroll
            for (int jj = 0; jj < 12; jj++) {
                float acc = 0.f;
#pragma unroll
                for (int t = 0; t < 4; t++) {
                    float2 f = h2f(uh[jj][t]);
                    acc = fmaf(f.x, vv[2 * t], acc);
                    acc = fmaf(f.y, vv[2 * t + 1], acc);
                }
                bij[jj] += acc;
            }
        }
    }

    if (LAYER == 0) {
        float a = v_od, b2 = v_od * v_od;
        blockReduceSum2(a, b2);
        float mu = a * (1.f / 256.f);
        float var = b2 * (1.f / 256.f) - mu * mu;
        g_emb2[(size_t)p * 256 + tid] = (v_od - mu) * rsqrtf(var + 1e-3f);
    } else {
        bool valid = (oo < O_REAL);
        float x = valid ? v_od : 0.f;
        float a = x, b2 = x * x;
        blockReduceSum2(a, b2);
        const float inv = 1.f / (float)(O_REAL * 8);
        float mu = a * inv;
        float var = b2 * inv - mu * mu;
        float vn = valid ? (x - mu) * rsqrtf(var + 1e-3f) : 0.f;
        float sq = vn * vn;
        sq += __shfl_xor_sync(0xffffffffu, sq, 1);
        sq += __shfl_xor_sync(0xffffffffu, sq, 2);
        sq += __shfl_xor_sync(0xffffffffu, sq, 4);
        if (dd == 0) slen[oo] = sqrtf(sq + 1e-6f);
        __syncthreads();
        if (tid < 32) {
            float l = (tid < O_REAL) ? slen[tid] : 0.f;
            float sa = l, sb = l * l;
#pragma unroll
            for (int off = 16; off; off >>= 1) {
                sa += __shfl_xor_sync(0xffffffffu, sa, off);
                sb += __shfl_xor_sync(0xffffffffu, sb, off);
            }
            float mu2 = sa / 31.f;
            float var2 = sb / 31.f - mu2 * mu2;
            if (tid < 31)
                out_final[(size_t)p * 31 + tid] = (l - mu2) * rsqrtf(var2 + 1e-3f);
        }
    }
}

// ---------------- launch ----------------
extern "C" void kernel_launch(void* const* d_in, const int* in_sizes, int n_in,
                              void* d_out, int out_size)
{
    (void)in_sizes; (void)n_in; (void)out_size;
    const float* inputs = (const float*)d_in[0];
    const float* c0w1 = (const float*)d_in[1];
    const float* c0b1 = (const float*)d_in[2];
    const float* c0w2 = (const float*)d_in[3];
    const float* c0b2 = (const float*)d_in[4];
    const float* c1w1 = (const float*)d_in[5];
    const float* c1b1 = (const float*)d_in[6];
    const float* c1w2 = (const float*)d_in[7];
    const float* c1b2 = (const float*)d_in[8];
    const float* pw   = (const float*)d_in[9];
    const float* pb   = (const float*)d_in[10];
    const float* ew1  = (const float*)d_in[11];
    const float* eb1  = (const float*)d_in[12];
    const float* ew2  = (const float*)d_in[13];
    const float* eb2  = (const float*)d_in[14];
    const float* W0   = (const float*)d_in[15];
    const float* B0   = (const float*)d_in[16];
    const float* W1   = (const float*)d_in[17];
    const float* B1   = (const float*)d_in[18];
    const int*   lens = (const int*)d_in[19];
    float* out = (float*)d_out;

    static cudaStream_t s2 = nullptr;
    static cudaEvent_t evStart = nullptr, evFork = nullptr, evJoin = nullptr, evC = nullptr;
    if (!s2) {
        cudaStreamCreateWithFlags(&s2, cudaStreamNonBlocking);
        cudaEventCreateWithFlags(&evStart, cudaEventDisableTiming);
        cudaEventCreateWithFlags(&evFork, cudaEventDisableTiming);
        cudaEventCreateWithFlags(&evJoin, cudaEventDisableTiming);
        cudaEventCreateWithFlags(&evC, cudaEventDisableTiming);
        cudaFuncSetAttribute(k_conv1, cudaFuncAttributeMaxDynamicSharedMemorySize, 52224);
    }

    // fork s2 into the capture graph FIRST, then k_const on s2
    cudaEventRecord(evStart, 0);
    cudaStreamWaitEvent(s2, evStart, 0);
    k_const<<<1, 256, 0, s2>>>(B0, W1, B1);
    cudaEventRecord(evC, s2);

    // head pipeline on stream 0
    k_prep<<<116, 256>>>(c1w1, c1w2, pw);
    k_conv0<<<2048, 256>>>(inputs, c0w1, c0b1, c0w2, c0b2, lens);
    k_conv1<<<2048, 128, 52224>>>(c1b1, c1b2, lens);
    k_proj<<<512, 256>>>(pb);
    k_enc<<<4096, 256>>>(ew1, eb1, ew2, eb2, lens);

    // fork: s2 waits for head pipeline; stream 0 waits for k_const
    cudaEventRecord(evFork, 0);
    cudaStreamWaitEvent(s2, evFork, 0);
    cudaStreamWaitEvent(0, evC, 0);

    // two independent chunk chains, overlapped on two streams (CHUNK=1024, L2-resident)
    for (int c = 0; c < NCHUNK; c++) {
        int base = c * CHUNK;
        int buf = c & 1;
        cudaStream_t st = (c & 1) ? s2 : (cudaStream_t)0;
        k_uhat<0><<<dim3(CHUNK / 64, 96), 256, 0, st>>>(W0, B0, base, buf, lens);
        k_route<0><<<CHUNK, 256, 0, st>>>(nullptr, base, buf, lens);
        k_uhat<1><<<dim3(CHUNK / 64, 96), 256, 0, st>>>(W1, B1, base, buf, lens);
        k_route<1><<<CHUNK, 256, 0, st>>>(out, base, buf, lens);
    }

    // join
    cudaEventRecord(evJoin, s2);
    cudaStreamWaitEvent(0, evJoin, 0);
}